// round 11
// baseline (speedup 1.0000x reference)
#include <cuda_runtime.h>

// Dense image warp (tfa.image.dense_image_warp), fp32.
// image: [B,H,W,C], flow: [B,H,W,2] (dy,dx). query = grid - flow.
//
// R8: 2 px/thread + __launch_bounds__(256,5) (regs<=51) to push occupancy
// 32% -> ~60% under the near-saturated L1 (88.5%). Access structure per px
// unchanged from the R7 winner: aligned 32B tap windows (2x LDG.128 +
// predicated tail), flow 1x LDG.128/thread, out 3x STG.64/thread.

constexpr int B = 8;
constexpr int H = 1024;
constexpr int W = 768;
constexpr int NPIX = B * H * W;           // 6291456, divisible by 2
constexpr int ROW3 = W * 3;               // 2304 floats, multiple of 4

__device__ __forceinline__ float sel4(bool o1, bool o2,
                                      float v0, float v1, float v2, float v3)
{
    float lo = o1 ? v1 : v0;
    float hi = o1 ? v3 : v2;
    return o2 ? hi : lo;
}

__global__ __launch_bounds__(256, 5) void warp_kernel(
    const float*  __restrict__ img,
    const float4* __restrict__ flow4,
    float2*       __restrict__ out2)
{
    int t = blockIdx.x * blockDim.x + threadIdx.x;   // one thread = 2 pixels
    int idx0 = t * 2;

    int xb  = idx0 % W;        // base x of the 2-pixel pair (W even -> same row)
    int row = idx0 / W;
    int y   = row % H;
    int b   = row / H;

    float4 f = __ldg(flow4 + t);           // (dy0,dx0,dy1,dx1)
    float dys[2] = {f.x, f.z};
    float dxs[2] = {f.y, f.w};

    float res[6];
    const float fy = (float)y;
    const int bh = b * H;

#pragma unroll
    for (int i = 0; i < 2; i++) {
        float qy = fy - dys[i];
        float qx = (float)(xb + i) - dxs[i];

        float y0f = fminf(fmaxf(floorf(qy), 0.0f), (float)(H - 2));
        float x0f = fminf(fmaxf(floorf(qx), 0.0f), (float)(W - 2));
        float ay  = fminf(fmaxf(qy - y0f, 0.0f), 1.0f);
        float ax  = fminf(fmaxf(qx - x0f, 0.0f), 1.0f);

        int y0 = (int)y0f;
        int x0 = (int)x0f;

        int pix3 = ((bh + y0) * W + x0) * 3;   // float index of tl[0]
        int a    = pix3 & ~3;                  // 16B-aligned window base
        int off  = pix3 & 3;
        bool o1 = (off & 1) != 0;
        bool o2 = (off & 2) != 0;
        bool o3 = (off == 3);

        const float4* pt = (const float4*)(img + a);
        const float4* pb = (const float4*)(img + a + ROW3);
        float4 t0 = __ldg(pt);
        float4 t1 = __ldg(pt + 1);
        float4 b0 = __ldg(pb);
        float4 b1 = __ldg(pb + 1);
        float tt = o3 ? __ldg(img + a + 8)        : 0.0f;  // predicated tail
        float bb = o3 ? __ldg(img + a + ROW3 + 8) : 0.0f;

        // route window -> taps (w_j = window[off + j])
        float tl0 = sel4(o1, o2, t0.x, t0.y, t0.z, t0.w);
        float tl1 = sel4(o1, o2, t0.y, t0.z, t0.w, t1.x);
        float tl2 = sel4(o1, o2, t0.z, t0.w, t1.x, t1.y);
        float tr0 = sel4(o1, o2, t0.w, t1.x, t1.y, t1.z);
        float tr1 = sel4(o1, o2, t1.x, t1.y, t1.z, t1.w);
        float tr2 = sel4(o1, o2, t1.y, t1.z, t1.w, tt);

        float bl0 = sel4(o1, o2, b0.x, b0.y, b0.z, b0.w);
        float bl1 = sel4(o1, o2, b0.y, b0.z, b0.w, b1.x);
        float bl2 = sel4(o1, o2, b0.z, b0.w, b1.x, b1.y);
        float br0 = sel4(o1, o2, b0.w, b1.x, b1.y, b1.z);
        float br1 = sel4(o1, o2, b1.x, b1.y, b1.z, b1.w);
        float br2 = sel4(o1, o2, b1.y, b1.z, b1.w, bb);

        float top0 = fmaf(ax, tr0 - tl0, tl0);
        float top1 = fmaf(ax, tr1 - tl1, tl1);
        float top2 = fmaf(ax, tr2 - tl2, tl2);
        float bot0 = fmaf(ax, br0 - bl0, bl0);
        float bot1 = fmaf(ax, br1 - bl1, bl1);
        float bot2 = fmaf(ax, br2 - bl2, bl2);

        res[i * 3 + 0] = fmaf(ay, bot0 - top0, top0);
        res[i * 3 + 1] = fmaf(ay, bot1 - top1, top1);
        res[i * 3 + 2] = fmaf(ay, bot2 - top2, top2);
    }

    float2* o = out2 + 3 * t;              // 24B/thread, 8B-aligned
    o[0] = make_float2(res[0], res[1]);
    o[1] = make_float2(res[2], res[3]);
    o[2] = make_float2(res[4], res[5]);
}

extern "C" void kernel_launch(void* const* d_in, const int* in_sizes, int n_in,
                              void* d_out, int out_size)
{
    const float*  img  = (const float*)d_in[0];
    const float4* flow = (const float4*)d_in[1];
    float2*       out  = (float2*)d_out;

    int nthreads = NPIX / 2;           // 3145728
    int threads  = 256;
    int blocks   = nthreads / threads; // 12288, exact
    warp_kernel<<<blocks, threads>>>(img, flow, out);
}

// round 14
// speedup vs baseline: 1.0842x; 1.0842x over previous
#include <cuda_runtime.h>

// Dense image warp (tfa.image.dense_image_warp), fp32.
// image: [B,H,W,C], flow: [B,H,W,2] (dy,dx). query = grid - flow.
//
// R10: R7 winner structure (4 px/thread, 16-deep batched tap loads,
// vector flow/out) with __launch_bounds__(256,4): regs<=64 lifts occupancy
// 32% -> ~44% while keeping the deep per-thread load batch that R8 showed
// is what actually drives L1 throughput.

constexpr int B = 8;
constexpr int H = 1024;
constexpr int W = 768;
constexpr int NPIX = B * H * W;           // 6291456, divisible by 4
constexpr int ROW3 = W * 3;               // 2304 floats, multiple of 4

__device__ __forceinline__ float sel4(bool o1, bool o2,
                                      float v0, float v1, float v2, float v3)
{
    float lo = o1 ? v1 : v0;
    float hi = o1 ? v3 : v2;
    return o2 ? hi : lo;
}

__global__ __launch_bounds__(256, 4) void warp_kernel(
    const float*  __restrict__ img,
    const float4* __restrict__ flow4,
    float4*       __restrict__ out4)
{
    int t = blockIdx.x * blockDim.x + threadIdx.x;   // one thread = 4 pixels
    int idx0 = t * 4;

    int xb  = idx0 % W;        // base x of the 4-pixel group
    int row = idx0 / W;
    int y   = row % H;
    int b   = row / H;

    float4 fA = __ldg(flow4 + 2 * t);
    float4 fB = __ldg(flow4 + 2 * t + 1);
    float dys[4] = {fA.x, fA.z, fB.x, fB.z};
    float dxs[4] = {fA.y, fA.w, fB.y, fB.w};

    float res[12];
    const float fy = (float)y;
    const int bh = b * H;

#pragma unroll
    for (int i = 0; i < 4; i++) {
        float qy = fy - dys[i];
        float qx = (float)(xb + i) - dxs[i];

        float y0f = fminf(fmaxf(floorf(qy), 0.0f), (float)(H - 2));
        float x0f = fminf(fmaxf(floorf(qx), 0.0f), (float)(W - 2));
        float ay  = fminf(fmaxf(qy - y0f, 0.0f), 1.0f);
        float ax  = fminf(fmaxf(qx - x0f, 0.0f), 1.0f);

        int y0 = (int)y0f;
        int x0 = (int)x0f;

        int pix3 = ((bh + y0) * W + x0) * 3;   // float index of tl[0]
        int a    = pix3 & ~3;                  // 16B-aligned window base
        int off  = pix3 & 3;
        bool o1 = (off & 1) != 0;
        bool o2 = (off & 2) != 0;
        bool o3 = (off == 3);

        const float4* pt = (const float4*)(img + a);
        const float4* pb = (const float4*)(img + a + ROW3);
        float4 t0 = __ldg(pt);
        float4 t1 = __ldg(pt + 1);
        float4 b0 = __ldg(pb);
        float4 b1 = __ldg(pb + 1);
        float tt = o3 ? __ldg(img + a + 8)        : 0.0f;  // predicated tail
        float bb = o3 ? __ldg(img + a + ROW3 + 8) : 0.0f;

        // route window -> taps (w_j = window[off + j])
        float tl0 = sel4(o1, o2, t0.x, t0.y, t0.z, t0.w);
        float tl1 = sel4(o1, o2, t0.y, t0.z, t0.w, t1.x);
        float tl2 = sel4(o1, o2, t0.z, t0.w, t1.x, t1.y);
        float tr0 = sel4(o1, o2, t0.w, t1.x, t1.y, t1.z);
        float tr1 = sel4(o1, o2, t1.x, t1.y, t1.z, t1.w);
        float tr2 = sel4(o1, o2, t1.y, t1.z, t1.w, tt);

        float bl0 = sel4(o1, o2, b0.x, b0.y, b0.z, b0.w);
        float bl1 = sel4(o1, o2, b0.y, b0.z, b0.w, b1.x);
        float bl2 = sel4(o1, o2, b0.z, b0.w, b1.x, b1.y);
        float br0 = sel4(o1, o2, b0.w, b1.x, b1.y, b1.z);
        float br1 = sel4(o1, o2, b1.x, b1.y, b1.z, b1.w);
        float br2 = sel4(o1, o2, b1.y, b1.z, b1.w, bb);

        float top0 = fmaf(ax, tr0 - tl0, tl0);
        float top1 = fmaf(ax, tr1 - tl1, tl1);
        float top2 = fmaf(ax, tr2 - tl2, tl2);
        float bot0 = fmaf(ax, br0 - bl0, bl0);
        float bot1 = fmaf(ax, br1 - bl1, bl1);
        float bot2 = fmaf(ax, br2 - bl2, bl2);

        res[i * 3 + 0] = fmaf(ay, bot0 - top0, top0);
        res[i * 3 + 1] = fmaf(ay, bot1 - top1, top1);
        res[i * 3 + 2] = fmaf(ay, bot2 - top2, top2);
    }

    float4* o = out4 + 3 * t;
    o[0] = make_float4(res[0], res[1],  res[2],  res[3]);
    o[1] = make_float4(res[4], res[5],  res[6],  res[7]);
    o[2] = make_float4(res[8], res[9],  res[10], res[11]);
}

extern "C" void kernel_launch(void* const* d_in, const int* in_sizes, int n_in,
                              void* d_out, int out_size)
{
    const float*  img  = (const float*)d_in[0];
    const float4* flow = (const float4*)d_in[1];
    float4*       out  = (float4*)d_out;

    int nthreads = NPIX / 4;           // 1572864
    int threads  = 256;
    int blocks   = nthreads / threads; // 6144, exact
    warp_kernel<<<blocks, threads>>>(img, flow, out);
}